// round 4
// baseline (speedup 1.0000x reference)
#include <cuda_runtime.h>
#include <math.h>

#define IN_DIM  2976
#define H1_DIM  5952
#define H2_DIM  1488
#define OUT_DIM 744
#define BATCH   8192

#define FEAT_F4 (OUT_DIM / 4)   // 186 float4 per feat row

typedef unsigned long long u64;

// ---------------------------------------------------------------------------
// packed f32x2 helpers (SASS FFMA2/FMUL2 path — only reachable via PTX)
// ---------------------------------------------------------------------------
__device__ __forceinline__ u64 pk(float lo, float hi) {
    u64 r; asm("mov.b64 %0, {%1,%2};" : "=l"(r) : "f"(lo), "f"(hi)); return r;
}
__device__ __forceinline__ void upk(u64 v, float& lo, float& hi) {
    asm("mov.b64 {%0,%1}, %2;" : "=f"(lo), "=f"(hi) : "l"(v));
}
__device__ __forceinline__ u64 pfma(u64 a, u64 b, u64 c) {
    u64 r; asm("fma.rn.f32x2 %0, %1, %2, %3;" : "=l"(r) : "l"(a), "l"(b), "l"(c)); return r;
}
__device__ __forceinline__ u64 pmul(u64 a, u64 b) {
    u64 r; asm("mul.rn.f32x2 %0, %1, %2;" : "=l"(r) : "l"(a), "l"(b)); return r;
}
__device__ __forceinline__ u64 padd(u64 a, u64 b) {
    u64 r; asm("add.rn.f32x2 %0, %1, %2;" : "=l"(r) : "l"(a), "l"(b)); return r;
}

// packed leaky_relu(0.01): lrelu(v) = 0.505*v + 0.495*|v|
//   v>=0: (0.505+0.495)*v = v   (to ~1 ulp)
//   v< 0: (0.505-0.495)*v = 0.01*v
__device__ __forceinline__ u64 plrelu(u64 v, u64 c505, u64 c495) {
    u64 t = pmul(v, c505);
    u64 a = v & 0x7FFFFFFF7FFFFFFFULL;   // packed fabs
    return pfma(a, c495, t);
}

__device__ __forceinline__ float lrelu(float v) {
    return fmaxf(v, 0.01f * v);
}

// ---------------------------------------------------------------------------
// Kernel 1: fused block-diagonal sparse MLP -> feat[b, k]
// Thread owns one k. Weights pre-splatted as (w,w) f32x2 pairs in registers.
// Each loop iteration processes TWO batch rows with packed math.
// ---------------------------------------------------------------------------
template <int B_TILE>
__global__ __launch_bounds__(256, 1)
void sparse_mlp_kernel(const float* __restrict__ x,
                       const float* __restrict__ W1,
                       const float* __restrict__ W2,
                       const float* __restrict__ W3,
                       float* __restrict__ feat)
{
    const int k = blockIdx.x * 256 + threadIdx.x;
    if (k >= OUT_DIM) return;

    // --- gather masked weights, splat to packed (w,w) ---
    u64 w1p[32];
#pragma unroll
    for (int j = 0; j < 8; j++) {
        const float4 q = *(const float4*)(W1 + (size_t)(8 * k + j) * IN_DIM + 4 * k);
        w1p[4 * j + 0] = pk(q.x, q.x);
        w1p[4 * j + 1] = pk(q.y, q.y);
        w1p[4 * j + 2] = pk(q.z, q.z);
        w1p[4 * j + 3] = pk(q.w, q.w);
    }
    u64 w2p[16];
    {
        float4 q;
        q = *(const float4*)(W2 + (size_t)(2 * k + 0) * H1_DIM + 8 * k + 0);
        w2p[0] = pk(q.x, q.x); w2p[1] = pk(q.y, q.y); w2p[2] = pk(q.z, q.z); w2p[3] = pk(q.w, q.w);
        q = *(const float4*)(W2 + (size_t)(2 * k + 0) * H1_DIM + 8 * k + 4);
        w2p[4] = pk(q.x, q.x); w2p[5] = pk(q.y, q.y); w2p[6] = pk(q.z, q.z); w2p[7] = pk(q.w, q.w);
        q = *(const float4*)(W2 + (size_t)(2 * k + 1) * H1_DIM + 8 * k + 0);
        w2p[8]  = pk(q.x, q.x); w2p[9]  = pk(q.y, q.y); w2p[10] = pk(q.z, q.z); w2p[11] = pk(q.w, q.w);
        q = *(const float4*)(W2 + (size_t)(2 * k + 1) * H1_DIM + 8 * k + 4);
        w2p[12] = pk(q.x, q.x); w2p[13] = pk(q.y, q.y); w2p[14] = pk(q.z, q.z); w2p[15] = pk(q.w, q.w);
    }
    u64 w3p[2];
    {
        const float2 q = *(const float2*)(W3 + (size_t)k * H2_DIM + 2 * k);
        w3p[0] = pk(q.x, q.x);
        w3p[1] = pk(q.y, q.y);
    }

    const u64 c505 = pk(0.505f, 0.505f);
    const u64 c495 = pk(0.495f, 0.495f);

    const int b0 = blockIdx.y * B_TILE;
    const float4* __restrict__ xr = (const float4*)x;  // row stride IN_DIM/4 = 744

#pragma unroll 2
    for (int p = 0; p < B_TILE / 2; p++) {
        const int b = b0 + 2 * p;
        // streaming loads: x is read exactly once, keep L2 for feat
        const float4 xa = __ldcs(xr + (size_t)b       * (IN_DIM / 4) + k);
        const float4 xb = __ldcs(xr + (size_t)(b + 1) * (IN_DIM / 4) + k);

        const u64 px0 = pk(xa.x, xb.x);
        const u64 px1 = pk(xa.y, xb.y);
        const u64 px2 = pk(xa.z, xb.z);
        const u64 px3 = pk(xa.w, xb.w);

        u64 a0 = 0ULL, a1 = 0ULL;   // (0.f, 0.f)
#pragma unroll
        for (int j = 0; j < 8; j++) {
            u64 v = pmul(w1p[4 * j + 0], px0);
            v = pfma(w1p[4 * j + 1], px1, v);
            v = pfma(w1p[4 * j + 2], px2, v);
            v = pfma(w1p[4 * j + 3], px3, v);
            v = plrelu(v, c505, c495);
            a0 = pfma(w2p[j],     v, a0);
            a1 = pfma(w2p[8 + j], v, a1);
        }
        a0 = plrelu(a0, c505, c495);
        a1 = plrelu(a1, c505, c495);
        u64 f = pmul(w3p[0], a0);
        f = pfma(w3p[1], a1, f);

        float fA, fB;
        upk(f, fA, fB);
        feat[(size_t)b       * OUT_DIM + k] = fA;
        feat[(size_t)(b + 1) * OUT_DIM + k] = fB;
    }
}

// ---------------------------------------------------------------------------
// Kernel 2: heads. Warp handles 2 rows, packed as f32x2 lanes (rowA, rowB).
// 17 packed dot products, packed butterfly reduce, lrelu + softmax epilogue.
// ---------------------------------------------------------------------------
__global__ __launch_bounds__(256)
void head_kernel(const float* __restrict__ feat,
                 const float* __restrict__ wo1, const float* __restrict__ bo1,
                 const float* __restrict__ wo2, const float* __restrict__ bo2,
                 const float* __restrict__ wo3, const float* __restrict__ bo3,
                 float* __restrict__ out_reg,
                 float* __restrict__ out_c1,
                 float* __restrict__ out_c2)
{
    const int warp = (blockIdx.x * blockDim.x + threadIdx.x) >> 5;
    const int lane = threadIdx.x & 31;
    const int r0 = warp * 2;
    if (r0 >= BATCH) return;

    const float4* __restrict__ f4 = (const float4*)feat;

    // load feat fragments for both rows, packed (rowA, rowB) per component
    u64 pf[6][4];
#pragma unroll
    for (int v = 0; v < 6; v++) {
        const int idx = v * 32 + lane;
        const bool ok = idx < FEAT_F4;
        const float4 fa = ok ? f4[(size_t)r0 * FEAT_F4 + idx]       : make_float4(0.f, 0.f, 0.f, 0.f);
        const float4 fb = ok ? f4[(size_t)(r0 + 1) * FEAT_F4 + idx] : make_float4(0.f, 0.f, 0.f, 0.f);
        pf[v][0] = pk(fa.x, fb.x);
        pf[v][1] = pk(fa.y, fb.y);
        pf[v][2] = pk(fa.z, fb.z);
        pf[v][3] = pk(fa.w, fb.w);
    }

    u64 acc[17];
#pragma unroll
    for (int o = 0; o < 17; o++) acc[o] = 0ULL;

    // reg head: wo2 rows 0..9 -> slots 0..9
#pragma unroll
    for (int o = 0; o < 10; o++) {
        const float4* wp = (const float4*)(wo2 + (size_t)o * OUT_DIM);
#pragma unroll
        for (int v = 0; v < 6; v++) {
            const int idx = v * 32 + lane;
            if (idx < FEAT_F4) {
                const float4 w = wp[idx];
                acc[o] = pfma(pk(w.x, w.x), pf[v][0], acc[o]);
                acc[o] = pfma(pk(w.y, w.y), pf[v][1], acc[o]);
                acc[o] = pfma(pk(w.z, w.z), pf[v][2], acc[o]);
                acc[o] = pfma(pk(w.w, w.w), pf[v][3], acc[o]);
            }
        }
    }
    // c1 head: wo1 rows 0..2 -> slots 10..12
#pragma unroll
    for (int o = 0; o < 3; o++) {
        const float4* wp = (const float4*)(wo1 + (size_t)o * OUT_DIM);
#pragma unroll
        for (int v = 0; v < 6; v++) {
            const int idx = v * 32 + lane;
            if (idx < FEAT_F4) {
                const float4 w = wp[idx];
                acc[10 + o] = pfma(pk(w.x, w.x), pf[v][0], acc[10 + o]);
                acc[10 + o] = pfma(pk(w.y, w.y), pf[v][1], acc[10 + o]);
                acc[10 + o] = pfma(pk(w.z, w.z), pf[v][2], acc[10 + o]);
                acc[10 + o] = pfma(pk(w.w, w.w), pf[v][3], acc[10 + o]);
            }
        }
    }
    // c2 head: wo3 rows 0..3 -> slots 13..16
#pragma unroll
    for (int o = 0; o < 4; o++) {
        const float4* wp = (const float4*)(wo3 + (size_t)o * OUT_DIM);
#pragma unroll
        for (int v = 0; v < 6; v++) {
            const int idx = v * 32 + lane;
            if (idx < FEAT_F4) {
                const float4 w = wp[idx];
                acc[13 + o] = pfma(pk(w.x, w.x), pf[v][0], acc[13 + o]);
                acc[13 + o] = pfma(pk(w.y, w.y), pf[v][1], acc[13 + o]);
                acc[13 + o] = pfma(pk(w.z, w.z), pf[v][2], acc[13 + o]);
                acc[13 + o] = pfma(pk(w.w, w.w), pf[v][3], acc[13 + o]);
            }
        }
    }

    // packed butterfly reduce: every lane ends with full (rowA, rowB) sums
#pragma unroll
    for (int o = 0; o < 17; o++) {
#pragma unroll
        for (int s = 16; s > 0; s >>= 1) {
            const u64 other = __shfl_xor_sync(0xffffffffu, acc[o], s);
            acc[o] = padd(acc[o], other);
        }
    }

    if (lane < 2) {
        const int r = r0 + lane;
        float res[17];
#pragma unroll
        for (int o = 0; o < 17; o++) {
            float lo, hi;
            upk(acc[o], lo, hi);
            res[o] = (lane == 0) ? lo : hi;
        }

        // reg = lrelu(feat @ wo2^T + bo2)
#pragma unroll
        for (int o = 0; o < 10; o++)
            out_reg[(size_t)r * 10 + o] = lrelu(res[o] + bo2[o]);

        // c1 = softmax(lrelu(feat @ wo1^T + bo1)) over 3
        {
            float z0 = lrelu(res[10] + bo1[0]);
            float z1 = lrelu(res[11] + bo1[1]);
            float z2 = lrelu(res[12] + bo1[2]);
            float m = fmaxf(z0, fmaxf(z1, z2));
            float e0 = __expf(z0 - m), e1 = __expf(z1 - m), e2 = __expf(z2 - m);
            float inv = 1.f / (e0 + e1 + e2);
            out_c1[(size_t)r * 3 + 0] = e0 * inv;
            out_c1[(size_t)r * 3 + 1] = e1 * inv;
            out_c1[(size_t)r * 3 + 2] = e2 * inv;
        }
        // c2 = softmax(lrelu(feat @ wo3^T + bo3)) over 4
        {
            float z0 = lrelu(res[13] + bo3[0]);
            float z1 = lrelu(res[14] + bo3[1]);
            float z2 = lrelu(res[15] + bo3[2]);
            float z3 = lrelu(res[16] + bo3[3]);
            float m = fmaxf(fmaxf(z0, z1), fmaxf(z2, z3));
            float e0 = __expf(z0 - m), e1 = __expf(z1 - m);
            float e2 = __expf(z2 - m), e3 = __expf(z3 - m);
            float inv = 1.f / (e0 + e1 + e2 + e3);
            out_c2[(size_t)r * 4 + 0] = e0 * inv;
            out_c2[(size_t)r * 4 + 1] = e1 * inv;
            out_c2[(size_t)r * 4 + 2] = e2 * inv;
            out_c2[(size_t)r * 4 + 3] = e3 * inv;
        }
    }
}

// ---------------------------------------------------------------------------
// launch
// ---------------------------------------------------------------------------
extern "C" void kernel_launch(void* const* d_in, const int* in_sizes, int n_in,
                              void* d_out, int out_size)
{
    // metadata order: x, W1, W2, W3, m1, m2, m3, wo1, bo1, wo2, bo2, wo3, bo3
    const float* x   = (const float*)d_in[0];
    const float* W1  = (const float*)d_in[1];
    const float* W2  = (const float*)d_in[2];
    const float* W3  = (const float*)d_in[3];
    const float* wo1 = (const float*)d_in[7];
    const float* bo1 = (const float*)d_in[8];
    const float* wo2 = (const float*)d_in[9];
    const float* bo2 = (const float*)d_in[10];
    const float* wo3 = (const float*)d_in[11];
    const float* bo3 = (const float*)d_in[12];

    float* out = (float*)d_out;
    // output layout: reg [B,10], c1 [B,3], c2 [B,4], feat [B,744]
    float* out_reg  = out;
    float* out_c1   = out + (size_t)BATCH * 10;
    float* out_c2   = out + (size_t)BATCH * 13;
    float* out_feat = out + (size_t)BATCH * 17;

    constexpr int B_TILE = 64;
    dim3 grid1((OUT_DIM + 255) / 256, BATCH / B_TILE);
    sparse_mlp_kernel<B_TILE><<<grid1, 256>>>(x, W1, W2, W3, out_feat);

    const int warps_needed = BATCH / 2;           // 2 rows per warp
    const int blocks2 = warps_needed / 8;         // 8 warps per block
    head_kernel<<<blocks2, 256>>>(out_feat, wo1, bo1, wo2, bo2, wo3, bo3,
                                  out_reg, out_c1, out_c2);
}

// round 5
// speedup vs baseline: 1.0728x; 1.0728x over previous
#include <cuda_runtime.h>
#include <math.h>

#define IN_DIM  2976
#define H1_DIM  5952
#define H2_DIM  1488
#define OUT_DIM 744
#define BATCH   8192

#define FEAT_F4 (OUT_DIM / 4)   // 186 float4 per feat row
#define N_HEAD  17              // 10 reg + 3 c1 + 4 c2

typedef unsigned long long u64;

// ---------------------------------------------------------------------------
// packed f32x2 helpers (SASS FFMA2 path — only reachable via PTX)
// ---------------------------------------------------------------------------
__device__ __forceinline__ u64 pk(float lo, float hi) {
    u64 r; asm("mov.b64 %0, {%1,%2};" : "=l"(r) : "f"(lo), "f"(hi)); return r;
}
__device__ __forceinline__ void upk(u64 v, float& lo, float& hi) {
    asm("mov.b64 {%0,%1}, %2;" : "=f"(lo), "=f"(hi) : "l"(v));
}
__device__ __forceinline__ u64 pfma(u64 a, u64 b, u64 c) {
    u64 r; asm("fma.rn.f32x2 %0, %1, %2, %3;" : "=l"(r) : "l"(a), "l"(b), "l"(c)); return r;
}
__device__ __forceinline__ u64 pmul(u64 a, u64 b) {
    u64 r; asm("mul.rn.f32x2 %0, %1, %2;" : "=l"(r) : "l"(a), "l"(b)); return r;
}
__device__ __forceinline__ u64 padd(u64 a, u64 b) {
    u64 r; asm("add.rn.f32x2 %0, %1, %2;" : "=l"(r) : "l"(a), "l"(b)); return r;
}

// packed leaky_relu(0.01): lrelu(v) = 0.505*v + 0.495*|v|  (exact cancellation)
__device__ __forceinline__ u64 plrelu(u64 v, u64 c505, u64 c495) {
    u64 t = pmul(v, c505);
    u64 a = v & 0x7FFFFFFF7FFFFFFFULL;   // packed fabs
    return pfma(a, c495, t);
}

__device__ __forceinline__ float lrelu(float v) {
    return fmaxf(v, 0.01f * v);
}

// ---------------------------------------------------------------------------
// pre-splatted head weights: g_wpk[o][k] = (w,w) as f32x2
// rows 0..9 = wo2 (reg), 10..12 = wo1 (c1), 13..16 = wo3 (c2)
// ---------------------------------------------------------------------------
__device__ __align__(16) u64 g_wpk[N_HEAD * OUT_DIM];

__global__ void prep_head_weights(const float* __restrict__ wo1,
                                  const float* __restrict__ wo2,
                                  const float* __restrict__ wo3)
{
    const int idx = blockIdx.x * 256 + threadIdx.x;
    if (idx >= N_HEAD * OUT_DIM) return;
    const int o = idx / OUT_DIM;
    const int k = idx - o * OUT_DIM;
    float w;
    if (o < 10)      w = wo2[o * OUT_DIM + k];
    else if (o < 13) w = wo1[(o - 10) * OUT_DIM + k];
    else             w = wo3[(o - 13) * OUT_DIM + k];
    g_wpk[idx] = pk(w, w);
}

// ---------------------------------------------------------------------------
// Kernel 1: fused block-diagonal sparse MLP -> feat[b, k]
// 128-thread blocks (occupancy: ~4 blocks/SM despite heavy weight regs).
// Each iteration loads 4 batch rows (MLP=4) and computes 2 packed pairs.
// ---------------------------------------------------------------------------
template <int B_TILE>
__global__ __launch_bounds__(128, 4)
void sparse_mlp_kernel(const float* __restrict__ x,
                       const float* __restrict__ W1,
                       const float* __restrict__ W2,
                       const float* __restrict__ W3,
                       float* __restrict__ feat)
{
    const int k = blockIdx.x * 128 + threadIdx.x;
    if (k >= OUT_DIM) return;

    // --- gather masked weights, splat to packed (w,w) ---
    u64 w1p[32];
#pragma unroll
    for (int j = 0; j < 8; j++) {
        const float4 q = *(const float4*)(W1 + (size_t)(8 * k + j) * IN_DIM + 4 * k);
        w1p[4 * j + 0] = pk(q.x, q.x);
        w1p[4 * j + 1] = pk(q.y, q.y);
        w1p[4 * j + 2] = pk(q.z, q.z);
        w1p[4 * j + 3] = pk(q.w, q.w);
    }
    u64 w2p[16];
    {
        float4 q;
        q = *(const float4*)(W2 + (size_t)(2 * k + 0) * H1_DIM + 8 * k + 0);
        w2p[0] = pk(q.x, q.x); w2p[1] = pk(q.y, q.y); w2p[2] = pk(q.z, q.z); w2p[3] = pk(q.w, q.w);
        q = *(const float4*)(W2 + (size_t)(2 * k + 0) * H1_DIM + 8 * k + 4);
        w2p[4] = pk(q.x, q.x); w2p[5] = pk(q.y, q.y); w2p[6] = pk(q.z, q.z); w2p[7] = pk(q.w, q.w);
        q = *(const float4*)(W2 + (size_t)(2 * k + 1) * H1_DIM + 8 * k + 0);
        w2p[8]  = pk(q.x, q.x); w2p[9]  = pk(q.y, q.y); w2p[10] = pk(q.z, q.z); w2p[11] = pk(q.w, q.w);
        q = *(const float4*)(W2 + (size_t)(2 * k + 1) * H1_DIM + 8 * k + 4);
        w2p[12] = pk(q.x, q.x); w2p[13] = pk(q.y, q.y); w2p[14] = pk(q.z, q.z); w2p[15] = pk(q.w, q.w);
    }
    u64 w3a, w3b;
    {
        const float2 q = *(const float2*)(W3 + (size_t)k * H2_DIM + 2 * k);
        w3a = pk(q.x, q.x);
        w3b = pk(q.y, q.y);
    }

    const u64 c505 = pk(0.505f, 0.505f);
    const u64 c495 = pk(0.495f, 0.495f);

    const int b0 = blockIdx.y * B_TILE;
    const float4* __restrict__ xr = (const float4*)x;  // row stride IN_DIM/4 = 744

#pragma unroll 2
    for (int g = 0; g < B_TILE / 4; g++) {
        const int b = b0 + 4 * g;
        // 4 independent streaming loads in flight (x is read exactly once)
        const float4 x0 = __ldcs(xr + (size_t)(b + 0) * (IN_DIM / 4) + k);
        const float4 x1 = __ldcs(xr + (size_t)(b + 1) * (IN_DIM / 4) + k);
        const float4 x2 = __ldcs(xr + (size_t)(b + 2) * (IN_DIM / 4) + k);
        const float4 x3 = __ldcs(xr + (size_t)(b + 3) * (IN_DIM / 4) + k);

        // pair A = rows (b, b+1), pair B = rows (b+2, b+3)
        const u64 pA0 = pk(x0.x, x1.x), pA1 = pk(x0.y, x1.y);
        const u64 pA2 = pk(x0.z, x1.z), pA3 = pk(x0.w, x1.w);
        const u64 pB0 = pk(x2.x, x3.x), pB1 = pk(x2.y, x3.y);
        const u64 pB2 = pk(x2.z, x3.z), pB3 = pk(x2.w, x3.w);

        u64 aA0 = 0ULL, aA1 = 0ULL, aB0 = 0ULL, aB1 = 0ULL;
#pragma unroll
        for (int j = 0; j < 8; j++) {
            u64 vA = pmul(w1p[4 * j + 0], pA0);
            u64 vB = pmul(w1p[4 * j + 0], pB0);
            vA = pfma(w1p[4 * j + 1], pA1, vA);
            vB = pfma(w1p[4 * j + 1], pB1, vB);
            vA = pfma(w1p[4 * j + 2], pA2, vA);
            vB = pfma(w1p[4 * j + 2], pB2, vB);
            vA = pfma(w1p[4 * j + 3], pA3, vA);
            vB = pfma(w1p[4 * j + 3], pB3, vB);
            vA = plrelu(vA, c505, c495);
            vB = plrelu(vB, c505, c495);
            aA0 = pfma(w2p[j],     vA, aA0);
            aA1 = pfma(w2p[8 + j], vA, aA1);
            aB0 = pfma(w2p[j],     vB, aB0);
            aB1 = pfma(w2p[8 + j], vB, aB1);
        }
        aA0 = plrelu(aA0, c505, c495);
        aA1 = plrelu(aA1, c505, c495);
        aB0 = plrelu(aB0, c505, c495);
        aB1 = plrelu(aB1, c505, c495);
        u64 fA = pmul(w3a, aA0); fA = pfma(w3b, aA1, fA);
        u64 fB = pmul(w3a, aB0); fB = pfma(w3b, aB1, fB);

        float f0, f1, f2, f3;
        upk(fA, f0, f1);
        upk(fB, f2, f3);
        feat[(size_t)(b + 0) * OUT_DIM + k] = f0;
        feat[(size_t)(b + 1) * OUT_DIM + k] = f1;
        feat[(size_t)(b + 2) * OUT_DIM + k] = f2;
        feat[(size_t)(b + 3) * OUT_DIM + k] = f3;
    }
}

// ---------------------------------------------------------------------------
// Kernel 2: heads. Warp handles 2 rows packed as f32x2 lanes (rowA, rowB).
// Chunk-outer loop keeps live feat regs small; weights come pre-splatted
// from g_wpk (no MOV splats in the hot loop).
// ---------------------------------------------------------------------------
__global__ __launch_bounds__(256)
void head_kernel(const float* __restrict__ feat,
                 const float* __restrict__ bo1,
                 const float* __restrict__ bo2,
                 const float* __restrict__ bo3,
                 float* __restrict__ out_reg,
                 float* __restrict__ out_c1,
                 float* __restrict__ out_c2)
{
    const int warp = (blockIdx.x * blockDim.x + threadIdx.x) >> 5;
    const int lane = threadIdx.x & 31;
    const int r0 = warp * 2;
    if (r0 >= BATCH) return;

    const float4* __restrict__ f4 = (const float4*)feat;

    u64 acc[N_HEAD];
#pragma unroll
    for (int o = 0; o < N_HEAD; o++) acc[o] = 0ULL;

#pragma unroll
    for (int v = 0; v < 6; v++) {
        const int idx = v * 32 + lane;
        if (idx < FEAT_F4) {
            const float4 fa = f4[(size_t)r0 * FEAT_F4 + idx];
            const float4 fb = f4[(size_t)(r0 + 1) * FEAT_F4 + idx];
            const u64 pf0 = pk(fa.x, fb.x);
            const u64 pf1 = pk(fa.y, fb.y);
            const u64 pf2 = pk(fa.z, fb.z);
            const u64 pf3 = pk(fa.w, fb.w);
#pragma unroll
            for (int o = 0; o < N_HEAD; o++) {
                const ulonglong2* wp = (const ulonglong2*)(g_wpk + o * OUT_DIM + 4 * idx);
                const ulonglong2 wq0 = wp[0];
                const ulonglong2 wq1 = wp[1];
                u64 a = acc[o];
                a = pfma(wq0.x, pf0, a);
                a = pfma(wq0.y, pf1, a);
                a = pfma(wq1.x, pf2, a);
                a = pfma(wq1.y, pf3, a);
                acc[o] = a;
            }
        }
    }

    // packed butterfly reduce: every lane ends with full (rowA, rowB) sums
#pragma unroll
    for (int o = 0; o < N_HEAD; o++) {
#pragma unroll
        for (int s = 16; s > 0; s >>= 1) {
            const u64 other = __shfl_xor_sync(0xffffffffu, acc[o], s);
            acc[o] = padd(acc[o], other);
        }
    }

    if (lane < 2) {
        const int r = r0 + lane;
        float res[N_HEAD];
#pragma unroll
        for (int o = 0; o < N_HEAD; o++) {
            float lo, hi;
            upk(acc[o], lo, hi);
            res[o] = (lane == 0) ? lo : hi;
        }

        // reg = lrelu(feat @ wo2^T + bo2)
#pragma unroll
        for (int o = 0; o < 10; o++)
            out_reg[(size_t)r * 10 + o] = lrelu(res[o] + bo2[o]);

        // c1 = softmax(lrelu(feat @ wo1^T + bo1)) over 3
        {
            float z0 = lrelu(res[10] + bo1[0]);
            float z1 = lrelu(res[11] + bo1[1]);
            float z2 = lrelu(res[12] + bo1[2]);
            float m = fmaxf(z0, fmaxf(z1, z2));
            float e0 = __expf(z0 - m), e1 = __expf(z1 - m), e2 = __expf(z2 - m);
            float inv = 1.f / (e0 + e1 + e2);
            out_c1[(size_t)r * 3 + 0] = e0 * inv;
            out_c1[(size_t)r * 3 + 1] = e1 * inv;
            out_c1[(size_t)r * 3 + 2] = e2 * inv;
        }
        // c2 = softmax(lrelu(feat @ wo3^T + bo3)) over 4
        {
            float z0 = lrelu(res[13] + bo3[0]);
            float z1 = lrelu(res[14] + bo3[1]);
            float z2 = lrelu(res[15] + bo3[2]);
            float z3 = lrelu(res[16] + bo3[3]);
            float m = fmaxf(fmaxf(z0, z1), fmaxf(z2, z3));
            float e0 = __expf(z0 - m), e1 = __expf(z1 - m);
            float e2 = __expf(z2 - m), e3 = __expf(z3 - m);
            float inv = 1.f / (e0 + e1 + e2 + e3);
            out_c2[(size_t)r * 4 + 0] = e0 * inv;
            out_c2[(size_t)r * 4 + 1] = e1 * inv;
            out_c2[(size_t)r * 4 + 2] = e2 * inv;
            out_c2[(size_t)r * 4 + 3] = e3 * inv;
        }
    }
}

// ---------------------------------------------------------------------------
// launch
// ---------------------------------------------------------------------------
extern "C" void kernel_launch(void* const* d_in, const int* in_sizes, int n_in,
                              void* d_out, int out_size)
{
    // metadata order: x, W1, W2, W3, m1, m2, m3, wo1, bo1, wo2, bo2, wo3, bo3
    const float* x   = (const float*)d_in[0];
    const float* W1  = (const float*)d_in[1];
    const float* W2  = (const float*)d_in[2];
    const float* W3  = (const float*)d_in[3];
    const float* wo1 = (const float*)d_in[7];
    const float* bo1 = (const float*)d_in[8];
    const float* wo2 = (const float*)d_in[9];
    const float* bo2 = (const float*)d_in[10];
    const float* wo3 = (const float*)d_in[11];
    const float* bo3 = (const float*)d_in[12];

    float* out = (float*)d_out;
    // output layout: reg [B,10], c1 [B,3], c2 [B,4], feat [B,744]
    float* out_reg  = out;
    float* out_c1   = out + (size_t)BATCH * 10;
    float* out_c2   = out + (size_t)BATCH * 13;
    float* out_feat = out + (size_t)BATCH * 17;

    // pre-splat head weights (tiny; runs concurrently-independent of MLP input)
    prep_head_weights<<<(N_HEAD * OUT_DIM + 255) / 256, 256>>>(wo1, wo2, wo3);

    constexpr int B_TILE = 32;
    dim3 grid1((OUT_DIM + 127) / 128, BATCH / B_TILE);
    sparse_mlp_kernel<B_TILE><<<grid1, 128>>>(x, W1, W2, W3, out_feat);

    const int warps_needed = BATCH / 2;           // 2 rows per warp
    const int blocks2 = warps_needed / 8;         // 8 warps per block
    head_kernel<<<blocks2, 256>>>(out_feat, bo1, bo2, bo3,
                                  out_reg, out_c1, out_c2);
}

// round 12
// speedup vs baseline: 1.2621x; 1.1764x over previous
#include <cuda_runtime.h>
#include <math.h>

#define IN_DIM  2976
#define H1_DIM  5952
#define H2_DIM  1488
#define OUT_DIM 744
#define BATCH   8192

#define FEAT_F4 (OUT_DIM / 4)   // 186 float4 per feat row
#define N_HEAD  17              // 10 reg + 3 c1 + 4 c2

typedef unsigned long long u64;

// ---------------------------------------------------------------------------
// packed f32x2 helpers (SASS FFMA2 — only reachable via PTX)
// ---------------------------------------------------------------------------
__device__ __forceinline__ u64 pfma(u64 a, u64 b, u64 c) {
    u64 r; asm("fma.rn.f32x2 %0, %1, %2, %3;" : "=l"(r) : "l"(a), "l"(b), "l"(c)); return r;
}
__device__ __forceinline__ u64 padd(u64 a, u64 b) {
    u64 r; asm("add.rn.f32x2 %0, %1, %2;" : "=l"(r) : "l"(a), "l"(b)); return r;
}
__device__ __forceinline__ void upk(u64 v, float& lo, float& hi) {
    asm("mov.b64 {%0,%1}, %2;" : "=f"(lo), "=f"(hi) : "l"(v));
}

__device__ __forceinline__ float lrelu(float v) {
    return fmaxf(v, 0.01f * v);   // FMUL + FMNMX — splits across fma/alu pipes
}
__device__ __forceinline__ float dot4(float4 a, float4 b) {
    return a.x * b.x + a.y * b.y + a.z * b.z + a.w * b.w;
}

// ---------------------------------------------------------------------------
// Kernel 1: fused block-diagonal sparse MLP -> feat[b, k]  (SCALAR math)
// Thread owns one k; 50 weight floats live in registers (no splat, no spill).
// 4 batch rows in flight per iteration (MLP=4) to hide streaming-x DRAM latency.
// B_TILE=16 divides BATCH exactly: grid.y = 512.
// ---------------------------------------------------------------------------
template <int B_TILE>
__global__ __launch_bounds__(128)
void sparse_mlp_kernel(const float* __restrict__ x,
                       const float* __restrict__ W1,
                       const float* __restrict__ W2,
                       const float* __restrict__ W3,
                       float* __restrict__ feat)
{
    const int k = blockIdx.x * 128 + threadIdx.x;
    if (k >= OUT_DIM) return;

    // --- gather masked weights into registers (scalar) ---
    float4 w1[8];
#pragma unroll
    for (int j = 0; j < 8; j++)
        w1[j] = *(const float4*)(W1 + (size_t)(8 * k + j) * IN_DIM + 4 * k);

    float w20[8], w21[8];
    {
        float4 q;
        q = *(const float4*)(W2 + (size_t)(2 * k + 0) * H1_DIM + 8 * k + 0);
        w20[0] = q.x; w20[1] = q.y; w20[2] = q.z; w20[3] = q.w;
        q = *(const float4*)(W2 + (size_t)(2 * k + 0) * H1_DIM + 8 * k + 4);
        w20[4] = q.x; w20[5] = q.y; w20[6] = q.z; w20[7] = q.w;
        q = *(const float4*)(W2 + (size_t)(2 * k + 1) * H1_DIM + 8 * k + 0);
        w21[0] = q.x; w21[1] = q.y; w21[2] = q.z; w21[3] = q.w;
        q = *(const float4*)(W2 + (size_t)(2 * k + 1) * H1_DIM + 8 * k + 4);
        w21[4] = q.x; w21[5] = q.y; w21[6] = q.z; w21[7] = q.w;
    }
    const float2 w3 = *(const float2*)(W3 + (size_t)k * H2_DIM + 2 * k);

    const int b0 = blockIdx.y * B_TILE;
    const float4* __restrict__ xr = (const float4*)x;  // row stride IN_DIM/4 = 744

    constexpr int MLP = 4;
    static_assert(B_TILE % MLP == 0, "tile divisible by MLP");
    for (int g = 0; g < B_TILE / MLP; g++) {
        const int b = b0 + MLP * g;
        // MLP independent streaming loads in flight (x is read exactly once)
        float4 xv[MLP];
#pragma unroll
        for (int t = 0; t < MLP; t++)
            xv[t] = __ldcs(xr + (size_t)(b + t) * (IN_DIM / 4) + k);

#pragma unroll
        for (int t = 0; t < MLP; t++) {
            float a0 = 0.f, a1 = 0.f;
#pragma unroll
            for (int j = 0; j < 8; j++) {
                const float v = lrelu(dot4(w1[j], xv[t]));
                a0 += w20[j] * v;
                a1 += w21[j] * v;
            }
            const float f = w3.x * lrelu(a0) + w3.y * lrelu(a1);
            feat[(size_t)(b + t) * OUT_DIM + k] = f;
        }
    }
}

// ---------------------------------------------------------------------------
// Kernel 2: heads. ONE row per warp. Packed f32x2 over the FEATURE axis:
// a 128-bit load of feat (or wo*) is already two f32x2 operands — zero
// packing overhead. 17 packed dot products, butterfly reduce, lo+hi fold.
// ---------------------------------------------------------------------------
__global__ __launch_bounds__(256)
void head_kernel(const float* __restrict__ feat,
                 const float* __restrict__ wo1, const float* __restrict__ bo1,
                 const float* __restrict__ wo2, const float* __restrict__ bo2,
                 const float* __restrict__ wo3, const float* __restrict__ bo3,
                 float* __restrict__ out_reg,
                 float* __restrict__ out_c1,
                 float* __restrict__ out_c2)
{
    const int warp = (blockIdx.x * blockDim.x + threadIdx.x) >> 5;
    const int lane = threadIdx.x & 31;
    const int r = warp;               // one batch row per warp
    if (r >= BATCH) return;

    // cache this row's feat fragment: 6 x 16B per lane
    const ulonglong2* __restrict__ fp =
        (const ulonglong2*)(feat + (size_t)r * OUT_DIM);
    ulonglong2 f[6];
#pragma unroll
    for (int v = 0; v < 6; v++) {
        const int idx = v * 32 + lane;
        if (idx < FEAT_F4) f[v] = fp[idx];
        else { f[v].x = 0ULL; f[v].y = 0ULL; }
    }

    u64 acc[N_HEAD];
#pragma unroll
    for (int o = 0; o < N_HEAD; o++) acc[o] = 0ULL;

    // head weight rows: 0..9 wo2, 10..12 wo1, 13..16 wo3
#pragma unroll
    for (int o = 0; o < N_HEAD; o++) {
        const float* wrow = (o < 10) ? (wo2 + (size_t)o * OUT_DIM)
                          : (o < 13) ? (wo1 + (size_t)(o - 10) * OUT_DIM)
                                     : (wo3 + (size_t)(o - 13) * OUT_DIM);
        const ulonglong2* __restrict__ wp = (const ulonglong2*)wrow;
        u64 a = acc[o];
#pragma unroll
        for (int v = 0; v < 6; v++) {
            const int idx = v * 32 + lane;
            if (idx < FEAT_F4) {
                const ulonglong2 w = wp[idx];
                a = pfma(w.x, f[v].x, a);
                a = pfma(w.y, f[v].y, a);
            }
        }
        acc[o] = a;
    }

    // butterfly reduce (packed)
#pragma unroll
    for (int o = 0; o < N_HEAD; o++) {
#pragma unroll
        for (int s = 16; s > 0; s >>= 1)
            acc[o] = padd(acc[o], __shfl_xor_sync(0xffffffffu, acc[o], s));
    }

    if (lane == 0) {
        float res[N_HEAD];
#pragma unroll
        for (int o = 0; o < N_HEAD; o++) {
            float lo, hi;
            upk(acc[o], lo, hi);
            res[o] = lo + hi;
        }

        // reg = lrelu(feat @ wo2^T + bo2)
#pragma unroll
        for (int o = 0; o < 10; o++)
            out_reg[(size_t)r * 10 + o] = lrelu(res[o] + bo2[o]);

        // c1 = softmax(lrelu(feat @ wo1^T + bo1)) over 3
        {
            float z0 = lrelu(res[10] + bo1[0]);
            float z1 = lrelu(res[11] + bo1[1]);
            float z2 = lrelu(res[12] + bo1[2]);
            float m = fmaxf(z0, fmaxf(z1, z2));
            float e0 = __expf(z0 - m), e1 = __expf(z1 - m), e2 = __expf(z2 - m);
            float inv = 1.f / (e0 + e1 + e2);
            out_c1[(size_t)r * 3 + 0] = e0 * inv;
            out_c1[(size_t)r * 3 + 1] = e1 * inv;
            out_c1[(size_t)r * 3 + 2] = e2 * inv;
        }
        // c2 = softmax(lrelu(feat @ wo3^T + bo3)) over 4
        {
            float z0 = lrelu(res[13] + bo3[0]);
            float z1 = lrelu(res[14] + bo3[1]);
            float z2 = lrelu(res[15] + bo3[2]);
            float z3 = lrelu(res[16] + bo3[3]);
            float m = fmaxf(fmaxf(z0, z1), fmaxf(z2, z3));
            float e0 = __expf(z0 - m), e1 = __expf(z1 - m);
            float e2 = __expf(z2 - m), e3 = __expf(z3 - m);
            float inv = 1.f / (e0 + e1 + e2 + e3);
            out_c2[(size_t)r * 4 + 0] = e0 * inv;
            out_c2[(size_t)r * 4 + 1] = e1 * inv;
            out_c2[(size_t)r * 4 + 2] = e2 * inv;
            out_c2[(size_t)r * 4 + 3] = e3 * inv;
        }
    }
}

// ---------------------------------------------------------------------------
// launch
// ---------------------------------------------------------------------------
extern "C" void kernel_launch(void* const* d_in, const int* in_sizes, int n_in,
                              void* d_out, int out_size)
{
    // metadata order: x, W1, W2, W3, m1, m2, m3, wo1, bo1, wo2, bo2, wo3, bo3
    const float* x   = (const float*)d_in[0];
    const float* W1  = (const float*)d_in[1];
    const float* W2  = (const float*)d_in[2];
    const float* W3  = (const float*)d_in[3];
    const float* wo1 = (const float*)d_in[7];
    const float* bo1 = (const float*)d_in[8];
    const float* wo2 = (const float*)d_in[9];
    const float* bo2 = (const float*)d_in[10];
    const float* wo3 = (const float*)d_in[11];
    const float* bo3 = (const float*)d_in[12];

    float* out = (float*)d_out;
    // output layout: reg [B,10], c1 [B,3], c2 [B,4], feat [B,744]
    float* out_reg  = out;
    float* out_c1   = out + (size_t)BATCH * 10;
    float* out_c2   = out + (size_t)BATCH * 13;
    float* out_feat = out + (size_t)BATCH * 17;

    constexpr int B_TILE = 16;                 // 8192 / 16 = 512 exactly
    static_assert(BATCH % B_TILE == 0, "B_TILE must divide BATCH");
    dim3 grid1((OUT_DIM + 127) / 128, BATCH / B_TILE);   // (6, 512) = 3072 blocks
    sparse_mlp_kernel<B_TILE><<<grid1, 128>>>(x, W1, W2, W3, out_feat);

    const int blocks2 = BATCH / 8;     // 1 row per warp, 8 warps per block
    head_kernel<<<blocks2, 256>>>(out_feat, wo1, bo1, wo2, bo2, wo3, bo3,
                                  out_reg, out_c1, out_c2);
}